// round 1
// baseline (speedup 1.0000x reference)
#include <cuda_runtime.h>
#include <math.h>

// Problem constants
#define Bb   8
#define SEQ  1024
#define Dd   768
#define Hh   12
#define Zz   64
#define Mm   3072
#define ROWS (Bb * SEQ)           // 8192
#define ATTN_BETA 0.125f          // 1/sqrt(64)

// Scratch (device globals: allocation-guard safe)
__device__ float  g_Q[ROWS * Dd];                  // 25 MB
__device__ float  g_K[ROWS * Dd];                  // 25 MB
__device__ float  g_Hs[(size_t)ROWS * Mm];         // 100 MB
__device__ double g_attn_sum;
__device__ double g_hn_sum;

__global__ void zero_sums_kernel() {
    g_attn_sum = 0.0;
    g_hn_sum   = 0.0;
}

// ---------------------------------------------------------------------------
// C = A[M,768] * Bw[N,768]^T  (both row-major). which: 0->g_Q, 1->g_K, 2->g_Hs
// Tile 64x64, BK=16, 256 threads, 4x4 microtile.
// grid = (N/64, M/64)
// ---------------------------------------------------------------------------
__global__ void sgemm_nt_kernel(const float* __restrict__ A,
                                const float* __restrict__ Bw,
                                int N, int which) {
    float* C = (which == 0) ? g_Q : (which == 1) ? g_K : g_Hs;

    __shared__ float As[16][64];
    __shared__ float Bs[16][64];

    const int tid = threadIdx.x;
    const int tx = tid & 15;
    const int ty = tid >> 4;
    const int m0 = blockIdx.y * 64;
    const int n0 = blockIdx.x * 64;

    // load mapping: each thread loads one float4 of A and one of B per k-step
    const int lrow = tid >> 2;        // 0..63
    const int lk   = (tid & 3) * 4;   // 0,4,8,12

    float acc[4][4];
#pragma unroll
    for (int i = 0; i < 4; ++i)
#pragma unroll
        for (int j = 0; j < 4; ++j) acc[i][j] = 0.0f;

    for (int k0 = 0; k0 < Dd; k0 += 16) {
        float4 av = *(const float4*)(A  + (size_t)(m0 + lrow) * Dd + k0 + lk);
        float4 bv = *(const float4*)(Bw + (size_t)(n0 + lrow) * Dd + k0 + lk);
        __syncthreads();
        As[lk + 0][lrow] = av.x; As[lk + 1][lrow] = av.y;
        As[lk + 2][lrow] = av.z; As[lk + 3][lrow] = av.w;
        Bs[lk + 0][lrow] = bv.x; Bs[lk + 1][lrow] = bv.y;
        Bs[lk + 2][lrow] = bv.z; Bs[lk + 3][lrow] = bv.w;
        __syncthreads();

#pragma unroll
        for (int kk = 0; kk < 16; ++kk) {
            float4 a = *(const float4*)(&As[kk][ty * 4]);
            float4 b = *(const float4*)(&Bs[kk][tx * 4]);
            float avr[4] = {a.x, a.y, a.z, a.w};
            float bvr[4] = {b.x, b.y, b.z, b.w};
#pragma unroll
            for (int i = 0; i < 4; ++i)
#pragma unroll
                for (int j = 0; j < 4; ++j)
                    acc[i][j] = fmaf(avr[i], bvr[j], acc[i][j]);
        }
    }

#pragma unroll
    for (int i = 0; i < 4; ++i) {
        float* crow = C + (size_t)(m0 + ty * 4 + i) * N + n0 + tx * 4;
#pragma unroll
        for (int j = 0; j < 4; ++j) crow[j] = acc[i][j];
    }
}

// ---------------------------------------------------------------------------
// Fused attention scores + online logsumexp.
// grid = (16 q-tiles, 12 heads, 8 batch), 256 threads.
// For block (b,h,q0): S[q,k] = sum_z Q[b*1024+q, h*64+z] * K[b*1024+k, h*64+z]
// online-lse over all k = 0..1023 with scale ATTN_BETA; block-sum -> atomic.
// ---------------------------------------------------------------------------
__global__ void attn_lse_kernel() {
    const int b  = blockIdx.z;
    const int h  = blockIdx.y;
    const int q0 = blockIdx.x * 64;

    __shared__ float Qs[64][64];   // [z][q]
    __shared__ float Ks[64][64];   // [z][k]
    __shared__ float red[16];

    const int tid = threadIdx.x;
    const int tx = tid & 15;
    const int ty = tid >> 4;

    const int lrow = tid >> 2;       // 0..63
    const int lz   = (tid & 3) * 16; // 0,16,32,48

    // Load Q tile once, transposed into [z][q]
    {
        const float* src = g_Q + (size_t)(b * SEQ + q0 + lrow) * Dd + h * Zz + lz;
#pragma unroll
        for (int u = 0; u < 4; ++u) {
            float4 v = *(const float4*)(src + u * 4);
            Qs[lz + u * 4 + 0][lrow] = v.x;
            Qs[lz + u * 4 + 1][lrow] = v.y;
            Qs[lz + u * 4 + 2][lrow] = v.z;
            Qs[lz + u * 4 + 3][lrow] = v.w;
        }
    }

    float m[4], s[4];
#pragma unroll
    for (int i = 0; i < 4; ++i) { m[i] = -1e30f; s[i] = 0.0f; }

    for (int kt = 0; kt < 16; ++kt) {
        __syncthreads();   // protect Ks from previous iteration's readers
        {
            const float* src = g_K + (size_t)(b * SEQ + kt * 64 + lrow) * Dd + h * Zz + lz;
#pragma unroll
            for (int u = 0; u < 4; ++u) {
                float4 v = *(const float4*)(src + u * 4);
                Ks[lz + u * 4 + 0][lrow] = v.x;
                Ks[lz + u * 4 + 1][lrow] = v.y;
                Ks[lz + u * 4 + 2][lrow] = v.z;
                Ks[lz + u * 4 + 3][lrow] = v.w;
            }
        }
        __syncthreads();

        float acc[4][4];
#pragma unroll
        for (int i = 0; i < 4; ++i)
#pragma unroll
            for (int j = 0; j < 4; ++j) acc[i][j] = 0.0f;

#pragma unroll 8
        for (int z = 0; z < 64; ++z) {
            float4 a = *(const float4*)(&Qs[z][ty * 4]);
            float4 bq = *(const float4*)(&Ks[z][tx * 4]);
            float avr[4] = {a.x, a.y, a.z, a.w};
            float bvr[4] = {bq.x, bq.y, bq.z, bq.w};
#pragma unroll
            for (int i = 0; i < 4; ++i)
#pragma unroll
                for (int j = 0; j < 4; ++j)
                    acc[i][j] = fmaf(avr[i], bvr[j], acc[i][j]);
        }

        // Online LSE per row; row q=ty*4+i is owned by the 16 lanes sharing ty
        // (tid = ty*16 + tx -> 16 consecutive lanes = shuffle group of 16).
#pragma unroll
        for (int i = 0; i < 4; ++i) {
            float v0 = acc[i][0] * ATTN_BETA;
            float v1 = acc[i][1] * ATTN_BETA;
            float v2 = acc[i][2] * ATTN_BETA;
            float v3 = acc[i][3] * ATTN_BETA;
            float lm = fmaxf(fmaxf(v0, v1), fmaxf(v2, v3));
#pragma unroll
            for (int o = 8; o > 0; o >>= 1)
                lm = fmaxf(lm, __shfl_xor_sync(0xffffffffu, lm, o, 16));
            float nm = fmaxf(m[i], lm);
            float ls = __expf(v0 - nm) + __expf(v1 - nm) +
                       __expf(v2 - nm) + __expf(v3 - nm);
#pragma unroll
            for (int o = 8; o > 0; o >>= 1)
                ls += __shfl_xor_sync(0xffffffffu, ls, o, 16);
            s[i] = s[i] * __expf(m[i] - nm) + ls;
            m[i] = nm;
        }
    }

    // Block reduce the 64 row-LSEs
    if (tx == 0) {
        float loc = 0.0f;
#pragma unroll
        for (int i = 0; i < 4; ++i) loc += m[i] + logf(s[i]);
        red[ty] = loc;
    }
    __syncthreads();
    if (tid == 0) {
        double t = 0.0;
#pragma unroll
        for (int i = 0; i < 16; ++i) t += (double)red[i];
        atomicAdd(&g_attn_sum, t);
    }
}

// ---------------------------------------------------------------------------
// Hopfield row LSE: one block per row of Hs[8192, 3072], 256 threads.
// v = beta_hn * Hs[row, :]; lse over 3072; atomicAdd into g_hn_sum.
// ---------------------------------------------------------------------------
__global__ void hn_lse_kernel(const float* __restrict__ beta_ptr) {
    const int row = blockIdx.x;
    const int tid = threadIdx.x;
    const float beta = beta_ptr[0];
    const float* r = g_Hs + (size_t)row * Mm;

    float vals[12];
    float lm = -1e30f;
#pragma unroll
    for (int u = 0; u < 12; ++u) {
        vals[u] = beta * r[tid + u * 256];
        lm = fmaxf(lm, vals[u]);
    }

    __shared__ float sm[256];
    sm[tid] = lm;
    __syncthreads();
    for (int st = 128; st > 0; st >>= 1) {
        if (tid < st) sm[tid] = fmaxf(sm[tid], sm[tid + st]);
        __syncthreads();
    }
    const float M = sm[0];
    __syncthreads();

    float ls = 0.0f;
#pragma unroll
    for (int u = 0; u < 12; ++u) ls += __expf(vals[u] - M);
    sm[tid] = ls;
    __syncthreads();
    for (int st = 128; st > 0; st >>= 1) {
        if (tid < st) sm[tid] += sm[tid + st];
        __syncthreads();
    }
    if (tid == 0) atomicAdd(&g_hn_sum, (double)(M + logf(sm[0])));
}

__global__ void finalize_kernel(const float* __restrict__ beta_ptr, float* out) {
    double beta = (double)beta_ptr[0];
    out[0] = (float)(-8.0 * g_attn_sum - (1.0 / beta) * g_hn_sum);
}

// ---------------------------------------------------------------------------
extern "C" void kernel_launch(void* const* d_in, const int* in_sizes, int n_in,
                              void* d_out, int out_size) {
    (void)in_sizes; (void)n_in; (void)out_size;
    const float* g    = (const float*)d_in[0];   // [8,1024,768]
    const float* wq   = (const float*)d_in[1];   // [12,64,768]
    const float* wk   = (const float*)d_in[2];   // [12,64,768]
    const float* w_hn = (const float*)d_in[3];   // [3072,768]
    const float* beta = (const float*)d_in[4];   // [1]
    float* out = (float*)d_out;

    zero_sums_kernel<<<1, 1>>>();

    // Projections: Q = g @ wq^T, K = g @ wk^T   (N = 768)
    sgemm_nt_kernel<<<dim3(Dd / 64, ROWS / 64), 256>>>(g, wq, Dd, 0);
    sgemm_nt_kernel<<<dim3(Dd / 64, ROWS / 64), 256>>>(g, wk, Dd, 1);

    // Hopfield GEMM: Hs = g @ w_hn^T   (N = 3072)
    sgemm_nt_kernel<<<dim3(Mm / 64, ROWS / 64), 256>>>(g, w_hn, Mm, 2);

    // Attention fused scores + LSE
    attn_lse_kernel<<<dim3(SEQ / 64, Hh, Bb), 256>>>();

    // Hopfield LSE
    hn_lse_kernel<<<ROWS, 256>>>(beta);

    finalize_kernel<<<1, 1>>>(beta, out);
}

// round 2
// speedup vs baseline: 6.4085x; 6.4085x over previous
#include <cuda_runtime.h>
#include <cuda_bf16.h>
#include <math.h>
#include <stdint.h>

// Problem constants
#define Bb   8
#define SEQ  1024
#define Dd   768
#define Hh   12
#define Zz   64
#define Mm   3072
#define ROWS (Bb * SEQ)           // 8192
#define ATTN_BETA 0.125f          // 1/sqrt(64)
#define LOG2E 1.4426950408889634f
#define LN2   0.6931471805599453f

// bf16 scratch (device globals: allocation-guard safe)
__device__ __nv_bfloat16 g_gb [(size_t)ROWS * Dd];    // 12.6 MB
__device__ __nv_bfloat16 g_wqb[Hh * Zz * Dd];         // 1.2 MB
__device__ __nv_bfloat16 g_wkb[Hh * Zz * Dd];
__device__ __nv_bfloat16 g_whnb[Mm * Dd];             // 4.7 MB
__device__ __nv_bfloat16 g_Qb [(size_t)ROWS * Dd];    // 12.6 MB
__device__ __nv_bfloat16 g_Kb [(size_t)ROWS * Dd];
__device__ __nv_bfloat16 g_Hb [(size_t)ROWS * Mm];    // 50 MB
__device__ double g_attn_sum;
__device__ double g_hn_sum;

__global__ void zero_sums_kernel() { g_attn_sum = 0.0; g_hn_sum = 0.0; }

// ---------------------------------------------------------------------------
// fp32 -> bf16 conversion, 4 elems/thread
// ---------------------------------------------------------------------------
__global__ void cvt_kernel(const float* __restrict__ src,
                           __nv_bfloat16* __restrict__ dst, int n) {
    int i = (blockIdx.x * blockDim.x + threadIdx.x) * 4;
    if (i < n) {
        float4 v = *(const float4*)(src + i);
        __nv_bfloat162* d2 = (__nv_bfloat162*)(dst + i);
        d2[0] = __float22bfloat162_rn(make_float2(v.x, v.y));
        d2[1] = __float22bfloat162_rn(make_float2(v.z, v.w));
    }
}

// ---------------------------------------------------------------------------
// PTX helpers
// ---------------------------------------------------------------------------
__device__ __forceinline__ uint32_t smem_u32(const void* p) {
    return (uint32_t)__cvta_generic_to_shared(p);
}
__device__ __forceinline__ void ldsm_x4(uint32_t& r0, uint32_t& r1,
                                        uint32_t& r2, uint32_t& r3, uint32_t addr) {
    asm volatile("ldmatrix.sync.aligned.m8n8.x4.shared.b16 {%0,%1,%2,%3}, [%4];"
                 : "=r"(r0), "=r"(r1), "=r"(r2), "=r"(r3) : "r"(addr));
}
__device__ __forceinline__ void mma_bf16(float* d, const uint32_t* a, const uint32_t* b) {
    asm volatile(
        "mma.sync.aligned.m16n8k16.row.col.f32.bf16.bf16.f32 "
        "{%0,%1,%2,%3}, {%4,%5,%6,%7}, {%8,%9}, {%0,%1,%2,%3};"
        : "+f"(d[0]), "+f"(d[1]), "+f"(d[2]), "+f"(d[3])
        : "r"(a[0]), "r"(a[1]), "r"(a[2]), "r"(a[3]), "r"(b[0]), "r"(b[1]));
}

// ---------------------------------------------------------------------------
// C[M,N](bf16) = A[M,768](bf16) * B[N,768](bf16)^T
// 128x128 block tile, BK=32, 256 threads (8 warps as 4x2), warp tile 32x64.
// grid = (N/128, M/128)
// ---------------------------------------------------------------------------
#define GLDS 40   // smem row stride (32 + 8 pad)

__global__ __launch_bounds__(256, 2)
void gemm_bf16_nt(const __nv_bfloat16* __restrict__ A,
                  const __nv_bfloat16* __restrict__ B,
                  __nv_bfloat16* __restrict__ C, int N) {
    __shared__ __nv_bfloat16 As[128 * GLDS];
    __shared__ __nv_bfloat16 Bs[128 * GLDS];

    const int tid  = threadIdx.x;
    const int warp = tid >> 5, lane = tid & 31;
    const int wm = warp >> 1, wn = warp & 1;
    const int m0 = blockIdx.y * 128, n0 = blockIdx.x * 128;

    // global load mapping: row = tid>>2 (+64), chunk = tid&3 (8 bf16 each)
    const int grow = tid >> 2;
    const int gcol = (tid & 3) * 8;
    const __nv_bfloat16* Ag = A + (size_t)(m0 + grow) * Dd + gcol;
    const __nv_bfloat16* Bg = B + (size_t)(n0 + grow) * Dd + gcol;
    const int soff0 = grow * GLDS + gcol;
    const int soff1 = soff0 + 64 * GLDS;

    float acc[2][8][4];
#pragma unroll
    for (int i = 0; i < 2; ++i)
#pragma unroll
        for (int j = 0; j < 8; ++j)
#pragma unroll
            for (int k = 0; k < 4; ++k) acc[i][j][k] = 0.0f;

    // ldmatrix address components
    const uint32_t as_b = smem_u32(As);
    const uint32_t bs_b = smem_u32(Bs);
    const int arow = wm * 32 + (lane & 15);
    const int acol = (lane >> 4) * 8;
    const int brow = wn * 64 + (lane >> 4) * 8 + (lane & 7);
    const int bcol = ((lane >> 3) & 1) * 8;

    // prologue: tile k0=0
    *(uint4*)(As + soff0) = *(const uint4*)(Ag);
    *(uint4*)(As + soff1) = *(const uint4*)(Ag + (size_t)64 * Dd);
    *(uint4*)(Bs + soff0) = *(const uint4*)(Bg);
    *(uint4*)(Bs + soff1) = *(const uint4*)(Bg + (size_t)64 * Dd);
    __syncthreads();

    for (int k0 = 0; k0 < Dd; k0 += 32) {
        uint4 pa0, pa1, pb0, pb1;
        const bool has_next = (k0 + 32) < Dd;
        if (has_next) {
            pa0 = *(const uint4*)(Ag + k0 + 32);
            pa1 = *(const uint4*)(Ag + (size_t)64 * Dd + k0 + 32);
            pb0 = *(const uint4*)(Bg + k0 + 32);
            pb1 = *(const uint4*)(Bg + (size_t)64 * Dd + k0 + 32);
        }

#pragma unroll
        for (int kk = 0; kk < 32; kk += 16) {
            uint32_t af[2][4];
#pragma unroll
            for (int mt = 0; mt < 2; ++mt)
                ldsm_x4(af[mt][0], af[mt][1], af[mt][2], af[mt][3],
                        as_b + (uint32_t)(((arow + mt * 16) * GLDS + acol + kk) * 2));
            uint32_t bfr[4][4];
#pragma unroll
            for (int j = 0; j < 4; ++j)
                ldsm_x4(bfr[j][0], bfr[j][1], bfr[j][2], bfr[j][3],
                        bs_b + (uint32_t)(((brow + j * 16) * GLDS + bcol + kk) * 2));
#pragma unroll
            for (int mt = 0; mt < 2; ++mt)
#pragma unroll
                for (int j = 0; j < 4; ++j) {
                    mma_bf16(acc[mt][2 * j],     af[mt], &bfr[j][0]);
                    mma_bf16(acc[mt][2 * j + 1], af[mt], &bfr[j][2]);
                }
        }
        __syncthreads();
        if (has_next) {
            *(uint4*)(As + soff0) = pa0;
            *(uint4*)(As + soff1) = pa1;
            *(uint4*)(Bs + soff0) = pb0;
            *(uint4*)(Bs + soff1) = pb1;
            __syncthreads();
        }
    }

    // epilogue: bf16 stores
#pragma unroll
    for (int mt = 0; mt < 2; ++mt) {
        const int r = m0 + wm * 32 + mt * 16 + (lane >> 2);
#pragma unroll
        for (int nt = 0; nt < 8; ++nt) {
            const int c = n0 + wn * 64 + nt * 8 + (lane & 3) * 2;
            *(__nv_bfloat162*)(C + (size_t)r * N + c) =
                __float22bfloat162_rn(make_float2(acc[mt][nt][0], acc[mt][nt][1]));
            *(__nv_bfloat162*)(C + (size_t)(r + 8) * N + c) =
                __float22bfloat162_rn(make_float2(acc[mt][nt][2], acc[mt][nt][3]));
        }
    }
}

// ---------------------------------------------------------------------------
// Fused attention scores (bf16 mma) + online logsumexp (exp2 domain).
// grid = (16 q-tiles, 12 heads, 8 batch), 256 threads (8 warps as 4x2).
// Block: q-tile 64 rows; loop 8 k-tiles of 128; warp tile 16(q) x 64(k).
// ---------------------------------------------------------------------------
#define ALDS 72   // smem row stride (64 + 8 pad)

__global__ __launch_bounds__(256, 2)
void attn_lse_kernel() {
    const int b  = blockIdx.z;
    const int h  = blockIdx.y;
    const int q0 = blockIdx.x * 64;

    __shared__ __nv_bfloat16 Qs[64 * ALDS];
    __shared__ __nv_bfloat16 Ks[128 * ALDS];
    __shared__ float red[2][64][2];

    const int tid  = threadIdx.x;
    const int warp = tid >> 5, lane = tid & 31;
    const int wm = warp >> 1, wn = warp & 1;
    const float SC = ATTN_BETA * LOG2E;

    // load Q tile 64x64 (512 16B-chunks)
    {
#pragma unroll
        for (int i = 0; i < 2; ++i) {
            int idx = tid + i * 256;
            int row = idx >> 3, ch = (idx & 7) * 8;
            *(uint4*)(Qs + row * ALDS + ch) =
                *(const uint4*)(g_Qb + (size_t)(b * SEQ + q0 + row) * Dd + h * Zz + ch);
        }
    }
    __syncthreads();

    // Q fragments in registers: 4 z-steps
    const uint32_t qs_b = smem_u32(Qs);
    const uint32_t ks_b = smem_u32(Ks);
    uint32_t qf[4][4];
    {
        const int arow = wm * 16 + (lane & 15);
        const int acol = (lane >> 4) * 8;
#pragma unroll
        for (int zs = 0; zs < 4; ++zs)
            ldsm_x4(qf[zs][0], qf[zs][1], qf[zs][2], qf[zs][3],
                    qs_b + (uint32_t)((arow * ALDS + acol + zs * 16) * 2));
    }

    const int brow = wn * 64 + (lane >> 4) * 8 + (lane & 7);
    const int bcol = ((lane >> 3) & 1) * 8;

    float mrun[2] = {-1e30f, -1e30f};
    float srun[2] = {0.0f, 0.0f};

    for (int kt = 0; kt < 8; ++kt) {
        __syncthreads();  // protect Ks from previous readers
#pragma unroll
        for (int i = 0; i < 4; ++i) {
            int idx = tid + i * 256;
            int row = idx >> 3, ch = (idx & 7) * 8;
            *(uint4*)(Ks + row * ALDS + ch) =
                *(const uint4*)(g_Kb + (size_t)(b * SEQ + kt * 128 + row) * Dd + h * Zz + ch);
        }
        __syncthreads();

        float acc[8][4];
#pragma unroll
        for (int j = 0; j < 8; ++j)
#pragma unroll
            for (int k = 0; k < 4; ++k) acc[j][k] = 0.0f;

#pragma unroll
        for (int zs = 0; zs < 4; ++zs) {
            uint32_t bfr[4][4];
#pragma unroll
            for (int j = 0; j < 4; ++j)
                ldsm_x4(bfr[j][0], bfr[j][1], bfr[j][2], bfr[j][3],
                        ks_b + (uint32_t)(((brow + j * 16) * ALDS + bcol + zs * 16) * 2));
#pragma unroll
            for (int j = 0; j < 4; ++j) {
                mma_bf16(acc[2 * j],     qf[zs], &bfr[j][0]);
                mma_bf16(acc[2 * j + 1], qf[zs], &bfr[j][2]);
            }
        }

        // online lse (log2 domain) for the two row-halves this lane owns
#pragma unroll
        for (int half = 0; half < 2; ++half) {
            float v[16];
#pragma unroll
            for (int j = 0; j < 8; ++j) {
                v[2 * j]     = acc[j][2 * half]     * SC;
                v[2 * j + 1] = acc[j][2 * half + 1] * SC;
            }
            float lm = v[0];
#pragma unroll
            for (int u = 1; u < 16; ++u) lm = fmaxf(lm, v[u]);
            lm = fmaxf(lm, __shfl_xor_sync(0xffffffffu, lm, 1));
            lm = fmaxf(lm, __shfl_xor_sync(0xffffffffu, lm, 2));
            float nm = fmaxf(mrun[half], lm);
            float ls = 0.0f;
#pragma unroll
            for (int u = 0; u < 16; ++u) ls += exp2f(v[u] - nm);
            ls += __shfl_xor_sync(0xffffffffu, ls, 1);
            ls += __shfl_xor_sync(0xffffffffu, ls, 2);
            srun[half] = srun[half] * exp2f(mrun[half] - nm) + ls;
            mrun[half] = nm;
        }
    }

    // combine across the two wn warps per row
    if ((lane & 3) == 0) {
        int r = wm * 16 + (lane >> 2);
        red[wn][r][0]     = mrun[0];
        red[wn][r][1]     = srun[0];
        red[wn][r + 8][0] = mrun[1];
        red[wn][r + 8][1] = srun[1];
    }
    __syncthreads();

    if (tid < 64) {
        float m0v = red[0][tid][0], s0v = red[0][tid][1];
        float m1v = red[1][tid][0], s1v = red[1][tid][1];
        float M = fmaxf(m0v, m1v);
        float S = s0v * exp2f(m0v - M) + s1v * exp2f(m1v - M);
        float lse = (M + log2f(S)) * LN2;   // natural-log lse
#pragma unroll
        for (int o = 16; o > 0; o >>= 1)
            lse += __shfl_xor_sync(0xffffffffu, lse, o);
        if ((tid & 31) == 0) atomicAdd(&g_attn_sum, (double)lse);
    }
}

// ---------------------------------------------------------------------------
// Hopfield row LSE over bf16 Hs [8192, 3072]
// ---------------------------------------------------------------------------
__global__ void hn_lse_kernel(const float* __restrict__ beta_ptr) {
    const int row = blockIdx.x;
    const int tid = threadIdx.x;
    const float beta = beta_ptr[0];
    const __nv_bfloat16* r = g_Hb + (size_t)row * Mm;

    float vals[12];
    float lm = -1e30f;
#pragma unroll
    for (int u = 0; u < 12; ++u) {
        vals[u] = beta * __bfloat162float(r[tid + u * 256]);
        lm = fmaxf(lm, vals[u]);
    }

    __shared__ float sm[256];
    sm[tid] = lm;
    __syncthreads();
    for (int st = 128; st > 0; st >>= 1) {
        if (tid < st) sm[tid] = fmaxf(sm[tid], sm[tid + st]);
        __syncthreads();
    }
    const float M = sm[0];
    __syncthreads();

    float ls = 0.0f;
#pragma unroll
    for (int u = 0; u < 12; ++u) ls += __expf(vals[u] - M);
    sm[tid] = ls;
    __syncthreads();
    for (int st = 128; st > 0; st >>= 1) {
        if (tid < st) sm[tid] += sm[tid + st];
        __syncthreads();
    }
    if (tid == 0) atomicAdd(&g_hn_sum, (double)(M + logf(sm[0])));
}

__global__ void finalize_kernel(const float* __restrict__ beta_ptr, float* out) {
    double beta = (double)beta_ptr[0];
    out[0] = (float)(-8.0 * g_attn_sum - (1.0 / beta) * g_hn_sum);
}

// ---------------------------------------------------------------------------
extern "C" void kernel_launch(void* const* d_in, const int* in_sizes, int n_in,
                              void* d_out, int out_size) {
    (void)in_sizes; (void)n_in; (void)out_size;
    const float* g    = (const float*)d_in[0];   // [8,1024,768]
    const float* wq   = (const float*)d_in[1];   // [12,64,768]
    const float* wk   = (const float*)d_in[2];   // [12,64,768]
    const float* w_hn = (const float*)d_in[3];   // [3072,768]
    const float* beta = (const float*)d_in[4];   // [1]
    float* out = (float*)d_out;

    // bf16 scratch pointers (device-symbol addresses are compile-time on device)
    __nv_bfloat16 *gb, *wqb, *wkb, *whnb, *Qb, *Kb, *Hb;
    cudaGetSymbolAddress((void**)&gb,   g_gb);
    cudaGetSymbolAddress((void**)&wqb,  g_wqb);
    cudaGetSymbolAddress((void**)&wkb,  g_wkb);
    cudaGetSymbolAddress((void**)&whnb, g_whnb);
    cudaGetSymbolAddress((void**)&Qb,   g_Qb);
    cudaGetSymbolAddress((void**)&Kb,   g_Kb);
    cudaGetSymbolAddress((void**)&Hb,   g_Hb);

    zero_sums_kernel<<<1, 1>>>();

    const int ng = ROWS * Dd, nw = Hh * Zz * Dd, nh = Mm * Dd;
    cvt_kernel<<<(ng / 4 + 255) / 256, 256>>>(g, gb, ng);
    cvt_kernel<<<(nw / 4 + 255) / 256, 256>>>(wq, wqb, nw);
    cvt_kernel<<<(nw / 4 + 255) / 256, 256>>>(wk, wkb, nw);
    cvt_kernel<<<(nh / 4 + 255) / 256, 256>>>(w_hn, whnb, nh);

    // Q = g @ wq^T, K = g @ wk^T (N = 768); Hs = g @ w_hn^T (N = 3072)
    gemm_bf16_nt<<<dim3(Dd / 128, ROWS / 128), 256>>>(gb, wqb, Qb, Dd);
    gemm_bf16_nt<<<dim3(Dd / 128, ROWS / 128), 256>>>(gb, wkb, Kb, Dd);
    gemm_bf16_nt<<<dim3(Mm / 128, ROWS / 128), 256>>>(gb, whnb, Hb, Mm);

    // Attention fused scores + LSE
    attn_lse_kernel<<<dim3(SEQ / 64, Hh, Bb), 256>>>();

    // Hopfield LSE
    hn_lse_kernel<<<ROWS, 256>>>(beta);

    finalize_kernel<<<1, 1>>>(beta, out);
}

// round 3
// speedup vs baseline: 7.1163x; 1.1104x over previous
#include <cuda_runtime.h>
#include <cuda_bf16.h>
#include <math.h>
#include <stdint.h>

// Problem constants
#define Bb   8
#define SEQ  1024
#define Dd   768
#define Hh   12
#define Zz   64
#define Mm   3072
#define ROWS (Bb * SEQ)           // 8192
#define QKN  (2 * Dd)             // 1536 (Q cols then K cols)
#define NTIL (Mm / 128)           // 24 hopfield n-tiles
#define ATTN_BETA 0.125f          // 1/sqrt(64)
#define LOG2E 1.4426950408889634f
#define LN2   0.6931471805599453f

// bf16 scratch (device globals: allocation-guard safe)
__device__ __nv_bfloat16 g_gb  [(size_t)ROWS * Dd];    // 12.6 MB
__device__ __nv_bfloat16 g_wqkb[QKN * Dd];             // 2.4 MB (wq rows 0-767, wk 768-1535)
__device__ __nv_bfloat16 g_whnb[Mm * Dd];              // 4.7 MB
__device__ __nv_bfloat16 g_QKb [(size_t)ROWS * QKN];   // 25 MB
__device__ float         g_hn_part[(size_t)ROWS * NTIL * 2];  // 1.5 MB (m,s) pairs
__device__ double g_attn_sum;
__device__ double g_hn_sum;

__global__ void zero_sums_kernel() { g_attn_sum = 0.0; g_hn_sum = 0.0; }

// ---------------------------------------------------------------------------
// fp32 -> bf16 conversion, 4 elems/thread
// ---------------------------------------------------------------------------
__global__ void cvt_kernel(const float* __restrict__ src,
                           __nv_bfloat16* __restrict__ dst, int n) {
    int i = (blockIdx.x * blockDim.x + threadIdx.x) * 4;
    if (i < n) {
        float4 v = *(const float4*)(src + i);
        __nv_bfloat162* d2 = (__nv_bfloat162*)(dst + i);
        d2[0] = __float22bfloat162_rn(make_float2(v.x, v.y));
        d2[1] = __float22bfloat162_rn(make_float2(v.z, v.w));
    }
}

// ---------------------------------------------------------------------------
// PTX helpers
// ---------------------------------------------------------------------------
__device__ __forceinline__ uint32_t smem_u32(const void* p) {
    return (uint32_t)__cvta_generic_to_shared(p);
}
__device__ __forceinline__ void ldsm_x4(uint32_t& r0, uint32_t& r1,
                                        uint32_t& r2, uint32_t& r3, uint32_t addr) {
    asm volatile("ldmatrix.sync.aligned.m8n8.x4.shared.b16 {%0,%1,%2,%3}, [%4];"
                 : "=r"(r0), "=r"(r1), "=r"(r2), "=r"(r3) : "r"(addr));
}
__device__ __forceinline__ void mma_bf16(float* d, const uint32_t* a, const uint32_t* b) {
    asm volatile(
        "mma.sync.aligned.m16n8k16.row.col.f32.bf16.bf16.f32 "
        "{%0,%1,%2,%3}, {%4,%5,%6,%7}, {%8,%9}, {%0,%1,%2,%3};"
        : "+f"(d[0]), "+f"(d[1]), "+f"(d[2]), "+f"(d[3])
        : "r"(a[0]), "r"(a[1]), "r"(a[2]), "r"(a[3]), "r"(b[0]), "r"(b[1]));
}

// ---------------------------------------------------------------------------
// GEMM: A[M,768](bf16) * B[N,768](bf16)^T
// 128x128 block tile, BK=32, 256 threads (8 warps as 4x2), warp tile 32x64.
// FUSE=false: store bf16 C.  FUSE=true: per-row (max,sum) exp2-domain partials
// of beta*score into g_hn_part (Hopfield LSE fusion; C unused).
// grid = (N/128, M/128)
// ---------------------------------------------------------------------------
#define GLDS 40   // smem row stride (32 + 8 pad)

template <bool FUSE>
__global__ __launch_bounds__(256, 2)
void gemm_bf16_nt(const __nv_bfloat16* __restrict__ A,
                  const __nv_bfloat16* __restrict__ B,
                  __nv_bfloat16* __restrict__ C, int N,
                  const float* __restrict__ beta_ptr) {
    __shared__ __nv_bfloat16 As[128 * GLDS];
    __shared__ __nv_bfloat16 Bs[128 * GLDS];
    __shared__ float red[2][128][2];   // only used when FUSE

    const int tid  = threadIdx.x;
    const int warp = tid >> 5, lane = tid & 31;
    const int wm = warp >> 1, wn = warp & 1;
    const int m0 = blockIdx.y * 128, n0 = blockIdx.x * 128;

    // global load mapping: row = tid>>2 (+64), chunk = tid&3 (8 bf16 each)
    const int grow = tid >> 2;
    const int gcol = (tid & 3) * 8;
    const __nv_bfloat16* Ag = A + (size_t)(m0 + grow) * Dd + gcol;
    const __nv_bfloat16* Bg = B + (size_t)(n0 + grow) * Dd + gcol;
    const int soff0 = grow * GLDS + gcol;
    const int soff1 = soff0 + 64 * GLDS;

    float acc[2][8][4];
#pragma unroll
    for (int i = 0; i < 2; ++i)
#pragma unroll
        for (int j = 0; j < 8; ++j)
#pragma unroll
            for (int k = 0; k < 4; ++k) acc[i][j][k] = 0.0f;

    // ldmatrix address components
    const uint32_t as_b = smem_u32(As);
    const uint32_t bs_b = smem_u32(Bs);
    const int arow = wm * 32 + (lane & 15);
    const int acol = (lane >> 4) * 8;
    const int brow = wn * 64 + (lane >> 4) * 8 + (lane & 7);
    const int bcol = ((lane >> 3) & 1) * 8;

    // prologue: tile k0=0
    *(uint4*)(As + soff0) = *(const uint4*)(Ag);
    *(uint4*)(As + soff1) = *(const uint4*)(Ag + (size_t)64 * Dd);
    *(uint4*)(Bs + soff0) = *(const uint4*)(Bg);
    *(uint4*)(Bs + soff1) = *(const uint4*)(Bg + (size_t)64 * Dd);
    __syncthreads();

    for (int k0 = 0; k0 < Dd; k0 += 32) {
        uint4 pa0, pa1, pb0, pb1;
        const bool has_next = (k0 + 32) < Dd;
        if (has_next) {
            pa0 = *(const uint4*)(Ag + k0 + 32);
            pa1 = *(const uint4*)(Ag + (size_t)64 * Dd + k0 + 32);
            pb0 = *(const uint4*)(Bg + k0 + 32);
            pb1 = *(const uint4*)(Bg + (size_t)64 * Dd + k0 + 32);
        }

#pragma unroll
        for (int kk = 0; kk < 32; kk += 16) {
            uint32_t af[2][4];
#pragma unroll
            for (int mt = 0; mt < 2; ++mt)
                ldsm_x4(af[mt][0], af[mt][1], af[mt][2], af[mt][3],
                        as_b + (uint32_t)(((arow + mt * 16) * GLDS + acol + kk) * 2));
            uint32_t bfr[4][4];
#pragma unroll
            for (int j = 0; j < 4; ++j)
                ldsm_x4(bfr[j][0], bfr[j][1], bfr[j][2], bfr[j][3],
                        bs_b + (uint32_t)(((brow + j * 16) * GLDS + bcol + kk) * 2));
#pragma unroll
            for (int mt = 0; mt < 2; ++mt)
#pragma unroll
                for (int j = 0; j < 4; ++j) {
                    mma_bf16(acc[mt][2 * j],     af[mt], &bfr[j][0]);
                    mma_bf16(acc[mt][2 * j + 1], af[mt], &bfr[j][2]);
                }
        }
        __syncthreads();
        if (has_next) {
            *(uint4*)(As + soff0) = pa0;
            *(uint4*)(As + soff1) = pa1;
            *(uint4*)(Bs + soff0) = pb0;
            *(uint4*)(Bs + soff1) = pb1;
            __syncthreads();
        }
    }

    if (!FUSE) {
        // epilogue: bf16 stores
#pragma unroll
        for (int mt = 0; mt < 2; ++mt) {
            const int r = m0 + wm * 32 + mt * 16 + (lane >> 2);
#pragma unroll
            for (int nt = 0; nt < 8; ++nt) {
                const int c = n0 + wn * 64 + nt * 8 + (lane & 3) * 2;
                *(__nv_bfloat162*)(C + (size_t)r * N + c) =
                    __float22bfloat162_rn(make_float2(acc[mt][nt][0], acc[mt][nt][1]));
                *(__nv_bfloat162*)(C + (size_t)(r + 8) * N + c) =
                    __float22bfloat162_rn(make_float2(acc[mt][nt][2], acc[mt][nt][3]));
            }
        }
    } else {
        // Fused Hopfield LSE partial: per row, over this block's 128 cols.
        // Work in exp2 domain: v = beta*score*LOG2E.
        const float SC = beta_ptr[0] * LOG2E;
#pragma unroll
        for (int mt = 0; mt < 2; ++mt) {
#pragma unroll
            for (int half = 0; half < 2; ++half) {
                // row (within 128-row block) owned by this lane's quad:
                const int rloc = wm * 32 + mt * 16 + half * 8 + (lane >> 2);
                float v[16];
#pragma unroll
                for (int nt = 0; nt < 8; ++nt) {
                    v[2 * nt]     = acc[mt][nt][2 * half]     * SC;
                    v[2 * nt + 1] = acc[mt][nt][2 * half + 1] * SC;
                }
                float lm = v[0];
#pragma unroll
                for (int u = 1; u < 16; ++u) lm = fmaxf(lm, v[u]);
                lm = fmaxf(lm, __shfl_xor_sync(0xffffffffu, lm, 1));
                lm = fmaxf(lm, __shfl_xor_sync(0xffffffffu, lm, 2));
                float ls = 0.0f;
#pragma unroll
                for (int u = 0; u < 16; ++u) ls += exp2f(v[u] - lm);
                ls += __shfl_xor_sync(0xffffffffu, ls, 1);
                ls += __shfl_xor_sync(0xffffffffu, ls, 2);
                if ((lane & 3) == 0) {
                    red[wn][rloc][0] = lm;
                    red[wn][rloc][1] = ls;
                }
            }
        }
        __syncthreads();
        if (tid < 128) {
            float ma = red[0][tid][0], sa = red[0][tid][1];
            float mb = red[1][tid][0], sb = red[1][tid][1];
            float M = fmaxf(ma, mb);
            float S = sa * exp2f(ma - M) + sb * exp2f(mb - M);
            float2* part = (float2*)g_hn_part;
            part[(size_t)(m0 + tid) * NTIL + blockIdx.x] = make_float2(M, S);
        }
    }
}

// ---------------------------------------------------------------------------
// Combine Hopfield partials: one thread per row (8192 rows x 24 tiles).
// Partials are exp2-domain; natural-log lse = LN2 * (m + log2(S)).
// ---------------------------------------------------------------------------
__global__ void hn_combine_kernel() {
    const int row = blockIdx.x * 256 + threadIdx.x;
    const float2* part = (const float2*)g_hn_part + (size_t)row * NTIL;
    float M = -1e30f;
#pragma unroll
    for (int t = 0; t < NTIL; ++t) M = fmaxf(M, part[t].x);
    float S = 0.0f;
#pragma unroll
    for (int t = 0; t < NTIL; ++t) S += part[t].y * exp2f(part[t].x - M);
    float lse = (M + log2f(S)) * LN2;

    // block reduce -> one atomic per block
    __shared__ float sm[256];
    sm[threadIdx.x] = lse;
    __syncthreads();
    for (int st = 128; st > 0; st >>= 1) {
        if (threadIdx.x < st) sm[threadIdx.x] += sm[threadIdx.x + st];
        __syncthreads();
    }
    if (threadIdx.x == 0) atomicAdd(&g_hn_sum, (double)sm[0]);
}

// ---------------------------------------------------------------------------
// Fused attention scores (bf16 mma) + online logsumexp (exp2 domain).
// grid = (16 q-tiles, 12 heads, 8 batch), 256 threads (8 warps as 4x2).
// Q/K live interleaved in g_QKb [ROWS, 1536]: Q at col h*64, K at 768 + h*64.
// ---------------------------------------------------------------------------
#define ALDS 72   // smem row stride (64 + 8 pad)

__global__ __launch_bounds__(256, 2)
void attn_lse_kernel() {
    const int b  = blockIdx.z;
    const int h  = blockIdx.y;
    const int q0 = blockIdx.x * 64;

    __shared__ __nv_bfloat16 Qs[64 * ALDS];
    __shared__ __nv_bfloat16 Ks[128 * ALDS];
    __shared__ float red[2][64][2];

    const int tid  = threadIdx.x;
    const int warp = tid >> 5, lane = tid & 31;
    const int wm = warp >> 1, wn = warp & 1;
    const float SC = ATTN_BETA * LOG2E;

    // load Q tile 64x64 (512 16B-chunks)
    {
#pragma unroll
        for (int i = 0; i < 2; ++i) {
            int idx = tid + i * 256;
            int row = idx >> 3, ch = (idx & 7) * 8;
            *(uint4*)(Qs + row * ALDS + ch) =
                *(const uint4*)(g_QKb + (size_t)(b * SEQ + q0 + row) * QKN + h * Zz + ch);
        }
    }
    __syncthreads();

    // Q fragments in registers: 4 z-steps
    const uint32_t qs_b = smem_u32(Qs);
    const uint32_t ks_b = smem_u32(Ks);
    uint32_t qf[4][4];
    {
        const int arow = wm * 16 + (lane & 15);
        const int acol = (lane >> 4) * 8;
#pragma unroll
        for (int zs = 0; zs < 4; ++zs)
            ldsm_x4(qf[zs][0], qf[zs][1], qf[zs][2], qf[zs][3],
                    qs_b + (uint32_t)((arow * ALDS + acol + zs * 16) * 2));
    }

    const int brow = wn * 64 + (lane >> 4) * 8 + (lane & 7);
    const int bcol = ((lane >> 3) & 1) * 8;

    float mrun[2] = {-1e30f, -1e30f};
    float srun[2] = {0.0f, 0.0f};

    for (int kt = 0; kt < 8; ++kt) {
        __syncthreads();  // protect Ks from previous readers
#pragma unroll
        for (int i = 0; i < 4; ++i) {
            int idx = tid + i * 256;
            int row = idx >> 3, ch = (idx & 7) * 8;
            *(uint4*)(Ks + row * ALDS + ch) =
                *(const uint4*)(g_QKb + (size_t)(b * SEQ + kt * 128 + row) * QKN
                                + Dd + h * Zz + ch);
        }
        __syncthreads();

        float acc[8][4];
#pragma unroll
        for (int j = 0; j < 8; ++j)
#pragma unroll
            for (int k = 0; k < 4; ++k) acc[j][k] = 0.0f;

#pragma unroll
        for (int zs = 0; zs < 4; ++zs) {
            uint32_t bfr[4][4];
#pragma unroll
            for (int j = 0; j < 4; ++j)
                ldsm_x4(bfr[j][0], bfr[j][1], bfr[j][2], bfr[j][3],
                        ks_b + (uint32_t)(((brow + j * 16) * ALDS + bcol + zs * 16) * 2));
#pragma unroll
            for (int j = 0; j < 4; ++j) {
                mma_bf16(acc[2 * j],     qf[zs], &bfr[j][0]);
                mma_bf16(acc[2 * j + 1], qf[zs], &bfr[j][2]);
            }
        }

        // online lse (log2 domain) for the two row-halves this lane owns
#pragma unroll
        for (int half = 0; half < 2; ++half) {
            float v[16];
#pragma unroll
            for (int j = 0; j < 8; ++j) {
                v[2 * j]     = acc[j][2 * half]     * SC;
                v[2 * j + 1] = acc[j][2 * half + 1] * SC;
            }
            float lm = v[0];
#pragma unroll
            for (int u = 1; u < 16; ++u) lm = fmaxf(lm, v[u]);
            lm = fmaxf(lm, __shfl_xor_sync(0xffffffffu, lm, 1));
            lm = fmaxf(lm, __shfl_xor_sync(0xffffffffu, lm, 2));
            float nm = fmaxf(mrun[half], lm);
            float ls = 0.0f;
#pragma unroll
            for (int u = 0; u < 16; ++u) ls += exp2f(v[u] - nm);
            ls += __shfl_xor_sync(0xffffffffu, ls, 1);
            ls += __shfl_xor_sync(0xffffffffu, ls, 2);
            srun[half] = srun[half] * exp2f(mrun[half] - nm) + ls;
            mrun[half] = nm;
        }
    }

    // combine across the two wn warps per row
    if ((lane & 3) == 0) {
        int r = wm * 16 + (lane >> 2);
        red[wn][r][0]     = mrun[0];
        red[wn][r][1]     = srun[0];
        red[wn][r + 8][0] = mrun[1];
        red[wn][r + 8][1] = srun[1];
    }
    __syncthreads();

    if (tid < 64) {
        float m0v = red[0][tid][0], s0v = red[0][tid][1];
        float m1v = red[1][tid][0], s1v = red[1][tid][1];
        float M = fmaxf(m0v, m1v);
        float S = s0v * exp2f(m0v - M) + s1v * exp2f(m1v - M);
        float lse = (M + log2f(S)) * LN2;   // natural-log lse
#pragma unroll
        for (int o = 16; o > 0; o >>= 1)
            lse += __shfl_xor_sync(0xffffffffu, lse, o);
        if ((tid & 31) == 0) atomicAdd(&g_attn_sum, (double)lse);
    }
}

__global__ void finalize_kernel(const float* __restrict__ beta_ptr, float* out) {
    double beta = (double)beta_ptr[0];
    out[0] = (float)(-8.0 * g_attn_sum - (1.0 / beta) * g_hn_sum);
}

// ---------------------------------------------------------------------------
extern "C" void kernel_launch(void* const* d_in, const int* in_sizes, int n_in,
                              void* d_out, int out_size) {
    (void)in_sizes; (void)n_in; (void)out_size;
    const float* g    = (const float*)d_in[0];   // [8,1024,768]
    const float* wq   = (const float*)d_in[1];   // [12,64,768]
    const float* wk   = (const float*)d_in[2];   // [12,64,768]
    const float* w_hn = (const float*)d_in[3];   // [3072,768]
    const float* beta = (const float*)d_in[4];   // [1]
    float* out = (float*)d_out;

    __nv_bfloat16 *gb, *wqkb, *whnb, *QKb;
    cudaGetSymbolAddress((void**)&gb,   g_gb);
    cudaGetSymbolAddress((void**)&wqkb, g_wqkb);
    cudaGetSymbolAddress((void**)&whnb, g_whnb);
    cudaGetSymbolAddress((void**)&QKb,  g_QKb);

    zero_sums_kernel<<<1, 1>>>();

    const int ng = ROWS * Dd, nw = Hh * Zz * Dd, nh = Mm * Dd;
    cvt_kernel<<<(ng / 4 + 255) / 256, 256>>>(g, gb, ng);
    cvt_kernel<<<(nw / 4 + 255) / 256, 256>>>(wq, wqkb, nw);        // rows 0-767
    cvt_kernel<<<(nw / 4 + 255) / 256, 256>>>(wk, wqkb + nw, nw);   // rows 768-1535
    cvt_kernel<<<(nh / 4 + 255) / 256, 256>>>(w_hn, whnb, nh);

    // [Q|K] = g @ [wq|wk]^T  (N = 1536)
    gemm_bf16_nt<false><<<dim3(QKN / 128, ROWS / 128), 256>>>(gb, wqkb, QKb, QKN, beta);

    // Hopfield GEMM with fused row-LSE partials (no H materialization)
    gemm_bf16_nt<true><<<dim3(Mm / 128, ROWS / 128), 256>>>(gb, whnb, nullptr, Mm, beta);

    // Attention fused scores + LSE
    attn_lse_kernel<<<dim3(SEQ / 64, Hh, Bb), 256>>>();

    // Combine Hopfield partials
    hn_combine_kernel<<<ROWS / 256, 256>>>();

    finalize_kernel<<<1, 1>>>(beta, out);
}

// round 5
// speedup vs baseline: 8.0549x; 1.1319x over previous
#include <cuda_runtime.h>
#include <cuda_bf16.h>
#include <math.h>
#include <stdint.h>

// Problem constants
#define Bb   8
#define SEQ  1024
#define Dd   768
#define Hh   12
#define Zz   64
#define Mm   3072
#define ROWS (Bb * SEQ)           // 8192
#define QKN  (2 * Dd)             // 1536 (Q cols then K cols)
#define NTIL (Mm / 128)           // 24 hopfield n-tiles (128-wide)
#define ATTN_BETA 0.125f          // 1/sqrt(64)
#define LOG2E 1.4426950408889634f
#define LN2   0.6931471805599453f

// bf16 scratch (device globals: allocation-guard safe)
__device__ __nv_bfloat16 g_gb  [(size_t)ROWS * Dd];    // 12.6 MB
__device__ __nv_bfloat16 g_wqkb[QKN * Dd];             // 2.4 MB
__device__ __nv_bfloat16 g_whnb[Mm * Dd];              // 4.7 MB
__device__ __nv_bfloat16 g_QKb [(size_t)ROWS * QKN];   // 25 MB
__device__ float         g_hn_part[(size_t)ROWS * NTIL * 2];  // (m,s) pairs
__device__ double g_attn_sum;
__device__ double g_hn_sum;

__global__ void zero_sums_kernel() { g_attn_sum = 0.0; g_hn_sum = 0.0; }

// ---------------------------------------------------------------------------
// fp32 -> bf16 conversion
// ---------------------------------------------------------------------------
__global__ void cvt_kernel(const float* __restrict__ src,
                           __nv_bfloat16* __restrict__ dst, int n) {
    int i = (blockIdx.x * blockDim.x + threadIdx.x) * 4;
    if (i < n) {
        float4 v = *(const float4*)(src + i);
        __nv_bfloat162* d2 = (__nv_bfloat162*)(dst + i);
        d2[0] = __float22bfloat162_rn(make_float2(v.x, v.y));
        d2[1] = __float22bfloat162_rn(make_float2(v.z, v.w));
    }
}

// ---------------------------------------------------------------------------
// PTX helpers
// ---------------------------------------------------------------------------
__device__ __forceinline__ uint32_t smem_u32(const void* p) {
    return (uint32_t)__cvta_generic_to_shared(p);
}
__device__ __forceinline__ void ldsm_x4(uint32_t& r0, uint32_t& r1,
                                        uint32_t& r2, uint32_t& r3, uint32_t addr) {
    asm volatile("ldmatrix.sync.aligned.m8n8.x4.shared.b16 {%0,%1,%2,%3}, [%4];"
                 : "=r"(r0), "=r"(r1), "=r"(r2), "=r"(r3) : "r"(addr));
}
__device__ __forceinline__ void mma_bf16(float* d, const uint32_t* a, const uint32_t* b) {
    asm volatile(
        "mma.sync.aligned.m16n8k16.row.col.f32.bf16.bf16.f32 "
        "{%0,%1,%2,%3}, {%4,%5,%6,%7}, {%8,%9}, {%0,%1,%2,%3};"
        : "+f"(d[0]), "+f"(d[1]), "+f"(d[2]), "+f"(d[3])
        : "r"(a[0]), "r"(a[1]), "r"(a[2]), "r"(a[3]), "r"(b[0]), "r"(b[1]));
}
__device__ __forceinline__ void cp16(uint32_t smem, const void* g) {
    asm volatile("cp.async.cg.shared.global [%0], [%1], 16;" :: "r"(smem), "l"(g));
}
__device__ __forceinline__ void cp_commit() {
    asm volatile("cp.async.commit_group;" ::: "memory");
}
template <int N>
__device__ __forceinline__ void cp_wait() {
    asm volatile("cp.async.wait_group %0;" :: "n"(N) : "memory");
}

// ---------------------------------------------------------------------------
// GEMM: A[M,768](bf16) * B[N,768](bf16)^T, 128x128 tile, BK=32, 256 threads,
// 8 warps (4x2), warp tile 32x64. cp.async 3-stage ring, ONE sync per chunk.
// FUSE=false: store bf16 C.  FUSE=true: fused Hopfield row-LSE partials.
// grid = (N/128, M/128)
// ---------------------------------------------------------------------------
#define GLDS 40            // smem row stride in elems (32 + 8 pad)
#define STG_B (128 * GLDS * 2)   // bytes per operand per stage (10240)
#define NCH   (Dd / 32)          // 24 chunks

template <bool FUSE>
__global__ __launch_bounds__(256, 2)
void gemm_bf16_nt(const __nv_bfloat16* __restrict__ A,
                  const __nv_bfloat16* __restrict__ B,
                  __nv_bfloat16* __restrict__ C, int N,
                  const float* __restrict__ beta_ptr) {
    extern __shared__ char dynsm[];
    // stage s: A at dynsm + s*2*STG_B, B at +STG_B
    __shared__ float red[2][128][2];   // only used when FUSE

    const int tid  = threadIdx.x;
    const int warp = tid >> 5, lane = tid & 31;
    const int wm = warp >> 1, wn = warp & 1;
    const int m0 = blockIdx.y * 128, n0 = blockIdx.x * 128;

    // cp.async load mapping: 2x16B per thread per operand per chunk
    // idx = tid + t*256 ; row = idx>>2 (0..127), c4 = idx&3 (16B unit)
    const int lrow0 = tid >> 2, lc4 = tid & 3;
    const __nv_bfloat16* Ag0 = A + (size_t)(m0 + lrow0) * Dd + lc4 * 8;
    const __nv_bfloat16* Ag1 = A + (size_t)(m0 + lrow0 + 64) * Dd + lc4 * 8;
    const __nv_bfloat16* Bg0 = B + (size_t)(n0 + lrow0) * Dd + lc4 * 8;
    const __nv_bfloat16* Bg1 = B + (size_t)(n0 + lrow0 + 64) * Dd + lc4 * 8;
    const uint32_t so0 = (uint32_t)(lrow0 * GLDS * 2 + lc4 * 16);
    const uint32_t so1 = so0 + (uint32_t)(64 * GLDS * 2);
    const uint32_t smbase = smem_u32(dynsm);

    float acc[2][8][4];
#pragma unroll
    for (int i = 0; i < 2; ++i)
#pragma unroll
        for (int j = 0; j < 8; ++j)
#pragma unroll
            for (int k = 0; k < 4; ++k) acc[i][j][k] = 0.0f;

    // ldmatrix address components (within a stage)
    const int arow = wm * 32 + (lane & 15);
    const int acol = (lane >> 4) * 8;
    const int brow = wn * 64 + (lane >> 4) * 8 + (lane & 7);
    const int bcol = ((lane >> 3) & 1) * 8;

    auto issue_chunk = [&](int j, int s) {
        const uint32_t ab = smbase + (uint32_t)(s * 2 * STG_B);
        const uint32_t bb = ab + STG_B;
        const int k0 = j * 32;
        cp16(ab + so0, Ag0 + k0);
        cp16(ab + so1, Ag1 + k0);
        cp16(bb + so0, Bg0 + k0);
        cp16(bb + so1, Bg1 + k0);
    };

    // prologue: chunks 0,1 into stages 0,1
    issue_chunk(0, 0); cp_commit();
    issue_chunk(1, 1); cp_commit();

    int stage = 0;
    for (int j = 0; j < NCH; ++j) {
        cp_wait<1>();        // chunk j landed (this thread's copies)
        __syncthreads();     // all threads' copies visible; compute j-1 closed
        if (j + 2 < NCH) issue_chunk(j + 2, (stage + 2) % 3);
        cp_commit();         // commit (possibly empty) to keep group counts aligned

        const uint32_t ab = smbase + (uint32_t)(stage * 2 * STG_B);
        const uint32_t bb = ab + STG_B;
#pragma unroll
        for (int kk = 0; kk < 32; kk += 16) {
            uint32_t af[2][4];
#pragma unroll
            for (int mt = 0; mt < 2; ++mt)
                ldsm_x4(af[mt][0], af[mt][1], af[mt][2], af[mt][3],
                        ab + (uint32_t)(((arow + mt * 16) * GLDS + acol + kk) * 2));
            uint32_t bfr[4][4];
#pragma unroll
            for (int jj = 0; jj < 4; ++jj)
                ldsm_x4(bfr[jj][0], bfr[jj][1], bfr[jj][2], bfr[jj][3],
                        bb + (uint32_t)(((brow + jj * 16) * GLDS + bcol + kk) * 2));
#pragma unroll
            for (int mt = 0; mt < 2; ++mt)
#pragma unroll
                for (int jj = 0; jj < 4; ++jj) {
                    mma_bf16(acc[mt][2 * jj],     af[mt], &bfr[jj][0]);
                    mma_bf16(acc[mt][2 * jj + 1], af[mt], &bfr[jj][2]);
                }
        }
        stage = (stage + 1) % 3;
    }

    if (!FUSE) {
#pragma unroll
        for (int mt = 0; mt < 2; ++mt) {
            const int r = m0 + wm * 32 + mt * 16 + (lane >> 2);
#pragma unroll
            for (int nt = 0; nt < 8; ++nt) {
                const int c = n0 + wn * 64 + nt * 8 + (lane & 3) * 2;
                *(__nv_bfloat162*)(C + (size_t)r * N + c) =
                    __float22bfloat162_rn(make_float2(acc[mt][nt][0], acc[mt][nt][1]));
                *(__nv_bfloat162*)(C + (size_t)(r + 8) * N + c) =
                    __float22bfloat162_rn(make_float2(acc[mt][nt][2], acc[mt][nt][3]));
            }
        }
    } else {
        // Fused Hopfield LSE partial over this block's 128 cols (exp2 domain).
        const float SC = beta_ptr[0] * LOG2E;
#pragma unroll
        for (int mt = 0; mt < 2; ++mt) {
#pragma unroll
            for (int half = 0; half < 2; ++half) {
                const int rloc = wm * 32 + mt * 16 + half * 8 + (lane >> 2);
                float v[16];
#pragma unroll
                for (int nt = 0; nt < 8; ++nt) {
                    v[2 * nt]     = acc[mt][nt][2 * half]     * SC;
                    v[2 * nt + 1] = acc[mt][nt][2 * half + 1] * SC;
                }
                float lm = v[0];
#pragma unroll
                for (int u = 1; u < 16; ++u) lm = fmaxf(lm, v[u]);
                lm = fmaxf(lm, __shfl_xor_sync(0xffffffffu, lm, 1));
                lm = fmaxf(lm, __shfl_xor_sync(0xffffffffu, lm, 2));
                float ls = 0.0f;
#pragma unroll
                for (int u = 0; u < 16; ++u) ls += exp2f(v[u] - lm);
                ls += __shfl_xor_sync(0xffffffffu, ls, 1);
                ls += __shfl_xor_sync(0xffffffffu, ls, 2);
                if ((lane & 3) == 0) {
                    red[wn][rloc][0] = lm;
                    red[wn][rloc][1] = ls;
                }
            }
        }
        __syncthreads();
        if (tid < 128) {
            float ma = red[0][tid][0], sa = red[0][tid][1];
            float mb = red[1][tid][0], sb = red[1][tid][1];
            float M = fmaxf(ma, mb);
            float S = sa * exp2f(ma - M) + sb * exp2f(mb - M);
            float2* part = (float2*)g_hn_part;
            part[(size_t)(m0 + tid) * NTIL + blockIdx.x] = make_float2(M, S);
        }
    }
}

// ---------------------------------------------------------------------------
// Combine Hopfield partials: one thread per row (8192 rows x 24 tiles).
// ---------------------------------------------------------------------------
__global__ void hn_combine_kernel() {
    const int row = blockIdx.x * 256 + threadIdx.x;
    const float2* part = (const float2*)g_hn_part + (size_t)row * NTIL;
    float M = -1e30f;
#pragma unroll
    for (int t = 0; t < NTIL; ++t) M = fmaxf(M, part[t].x);
    float S = 0.0f;
#pragma unroll
    for (int t = 0; t < NTIL; ++t) S += part[t].y * exp2f(part[t].x - M);
    float lse = (M + log2f(S)) * LN2;

    __shared__ float smr[256];
    smr[threadIdx.x] = lse;
    __syncthreads();
    for (int st = 128; st > 0; st >>= 1) {
        if (threadIdx.x < st) smr[threadIdx.x] += smr[threadIdx.x + st];
        __syncthreads();
    }
    if (threadIdx.x == 0) atomicAdd(&g_hn_sum, (double)smr[0]);
}

// ---------------------------------------------------------------------------
// Fused attention scores (bf16 mma) + online logsumexp (exp2 domain).
// grid = (16 q-tiles, 12 heads, 8 batch), 256 threads (8 warps as 4x2).
// K tiles streamed with cp.async double buffer, one K-load sync per tile.
// ---------------------------------------------------------------------------
#define ALDS 72   // smem row stride (64 + 8 pad)

__global__ __launch_bounds__(256, 2)
void attn_lse_kernel() {
    const int b  = blockIdx.z;
    const int h  = blockIdx.y;
    const int q0 = blockIdx.x * 64;

    __shared__ __nv_bfloat16 Qs[64 * ALDS];
    __shared__ __nv_bfloat16 Ks[2][128 * ALDS];
    __shared__ float red[2][64][2];

    const int tid  = threadIdx.x;
    const int warp = tid >> 5, lane = tid & 31;
    const int wm = warp >> 1, wn = warp & 1;
    const float SC = ATTN_BETA * LOG2E;

    // K cp.async mapping: 4x16B per thread per tile
    const int krow = tid >> 1;              // 0..127 (with t offsets)
    // use idx = tid + t*256: row = idx>>3? (1024 chunks) -> row=idx>>3, ch=(idx&7)*8
    const __nv_bfloat16* Kbase = g_QKb + (size_t)(b * SEQ) * QKN + Dd + h * Zz;

    auto issue_k = [&](int kt, int s) {
#pragma unroll
        for (int t = 0; t < 4; ++t) {
            int idx = tid + t * 256;
            int row = idx >> 3, ch = (idx & 7) * 8;
            cp16(smem_u32(&Ks[s][row * ALDS + ch]),
                 Kbase + (size_t)(kt * 128 + row) * QKN + ch);
        }
    };

    // load Q tile 64x64 via cp.async too
    {
#pragma unroll
        for (int i = 0; i < 2; ++i) {
            int idx = tid + i * 256;
            int row = idx >> 3, ch = (idx & 7) * 8;
            cp16(smem_u32(&Qs[row * ALDS + ch]),
                 g_QKb + (size_t)(b * SEQ + q0 + row) * QKN + h * Zz + ch);
        }
        cp_commit();
    }
    issue_k(0, 0); cp_commit();

    // wait for Q (allow K0 still in flight), then build Q fragments
    cp_wait<1>();
    __syncthreads();

    const uint32_t qs_b = smem_u32(Qs);
    uint32_t qf[4][4];
    {
        const int arow = wm * 16 + (lane & 15);
        const int acol = (lane >> 4) * 8;
#pragma unroll
        for (int zs = 0; zs < 4; ++zs)
            ldsm_x4(qf[zs][0], qf[zs][1], qf[zs][2], qf[zs][3],
                    qs_b + (uint32_t)((arow * ALDS + acol + zs * 16) * 2));
    }

    const int brow = wn * 64 + (lane >> 4) * 8 + (lane & 7);
    const int bcol = ((lane >> 3) & 1) * 8;

    float mrun[2] = {-1e30f, -1e30f};
    float srun[2] = {0.0f, 0.0f};

    for (int kt = 0; kt < 8; ++kt) {
        cp_wait<0>();        // K tile kt landed
        __syncthreads();     // visible to all; previous compute closed
        if (kt + 1 < 8) issue_k(kt + 1, (kt + 1) & 1);
        cp_commit();

        const uint32_t ks_b = smem_u32(Ks[kt & 1]);

        float acc[8][4];
#pragma unroll
        for (int j = 0; j < 8; ++j)
#pragma unroll
            for (int k = 0; k < 4; ++k) acc[j][k] = 0.0f;

#pragma unroll
        for (int zs = 0; zs < 4; ++zs) {
            uint32_t bfr[4][4];
#pragma unroll
            for (int j = 0; j < 4; ++j)
                ldsm_x4(bfr[j][0], bfr[j][1], bfr[j][2], bfr[j][3],
                        ks_b + (uint32_t)(((brow + j * 16) * ALDS + bcol + zs * 16) * 2));
#pragma unroll
            for (int j = 0; j < 4; ++j) {
                mma_bf16(acc[2 * j],     qf[zs], &bfr[j][0]);
                mma_bf16(acc[2 * j + 1], qf[zs], &bfr[j][2]);
            }
        }

#pragma unroll
        for (int half = 0; half < 2; ++half) {
            float v[16];
#pragma unroll
            for (int j = 0; j < 8; ++j) {
                v[2 * j]     = acc[j][2 * half]     * SC;
                v[2 * j + 1] = acc[j][2 * half + 1] * SC;
            }
            float lm = v[0];
#pragma unroll
            for (int u = 1; u < 16; ++u) lm = fmaxf(lm, v[u]);
            lm = fmaxf(lm, __shfl_xor_sync(0xffffffffu, lm, 1));
            lm = fmaxf(lm, __shfl_xor_sync(0xffffffffu, lm, 2));
            float nm = fmaxf(mrun[half], lm);
            float ls = 0.0f;
#pragma unroll
            for (int u = 0; u < 16; ++u) ls += exp2f(v[u] - nm);
            ls += __shfl_xor_sync(0xffffffffu, ls, 1);
            ls += __shfl_xor_sync(0xffffffffu, ls, 2);
            srun[half] = srun[half] * exp2f(mrun[half] - nm) + ls;
            mrun[half] = nm;
        }
    }

    if ((lane & 3) == 0) {
        int r = wm * 16 + (lane >> 2);
        red[wn][r][0]     = mrun[0];
        red[wn][r][1]     = srun[0];
        red[wn][r + 8][0] = mrun[1];
        red[wn][r + 8][1] = srun[1];
    }
    __syncthreads();

    if (tid < 64) {
        float m0v = red[0][tid][0], s0v = red[0][tid][1];
        float m1v = red[1][tid][0], s1v = red[1][tid][1];
        float M = fmaxf(m0v, m1v);
        float S = s0v * exp2f(m0v - M) + s1v * exp2f(m1v - M);
        float lse = (M + log2f(S)) * LN2;
#pragma unroll
        for (int o = 16; o > 0; o >>= 1)
            lse += __shfl_xor_sync(0xffffffffu, lse, o);
        if ((tid & 31) == 0) atomicAdd(&g_attn_sum, (double)lse);
    }
}

__global__ void finalize_kernel(const float* __restrict__ beta_ptr, float* out) {
    double beta = (double)beta_ptr[0];
    out[0] = (float)(-8.0 * g_attn_sum - (1.0 / beta) * g_hn_sum);
}

// ---------------------------------------------------------------------------
extern "C" void kernel_launch(void* const* d_in, const int* in_sizes, int n_in,
                              void* d_out, int out_size) {
    (void)in_sizes; (void)n_in; (void)out_size;
    const float* g    = (const float*)d_in[0];
    const float* wq   = (const float*)d_in[1];
    const float* wk   = (const float*)d_in[2];
    const float* w_hn = (const float*)d_in[3];
    const float* beta = (const float*)d_in[4];
    float* out = (float*)d_out;

    __nv_bfloat16 *gb, *wqkb, *whnb, *QKb;
    cudaGetSymbolAddress((void**)&gb,   g_gb);
    cudaGetSymbolAddress((void**)&wqkb, g_wqkb);
    cudaGetSymbolAddress((void**)&whnb, g_whnb);
    cudaGetSymbolAddress((void**)&QKb,  g_QKb);

    const int SMEM_DYN = 3 * 2 * STG_B;   // 61440 B
    cudaFuncSetAttribute(gemm_bf16_nt<false>,
                         cudaFuncAttributeMaxDynamicSharedMemorySize, SMEM_DYN);
    cudaFuncSetAttribute(gemm_bf16_nt<true>,
                         cudaFuncAttributeMaxDynamicSharedMemorySize, SMEM_DYN);

    zero_sums_kernel<<<1, 1>>>();

    const int ng = ROWS * Dd, nw = Hh * Zz * Dd, nh = Mm * Dd;
    cvt_kernel<<<(ng / 4 + 255) / 256, 256>>>(g, gb, ng);
    cvt_kernel<<<(nw / 4 + 255) / 256, 256>>>(wq, wqkb, nw);
    cvt_kernel<<<(nw / 4 + 255) / 256, 256>>>(wk, wqkb + nw, nw);
    cvt_kernel<<<(nh / 4 + 255) / 256, 256>>>(w_hn, whnb, nh);

    // [Q|K] = g @ [wq|wk]^T  (N = 1536)
    gemm_bf16_nt<false><<<dim3(QKN / 128, ROWS / 128), 256, SMEM_DYN>>>(gb, wqkb, QKb, QKN, beta);

    // Hopfield GEMM with fused row-LSE partials (no H materialization)
    gemm_bf16_nt<true><<<dim3(Mm / 128, ROWS / 128), 256, SMEM_DYN>>>(gb, whnb, nullptr, Mm, beta);

    // Attention fused scores + LSE
    attn_lse_kernel<<<dim3(SEQ / 64, Hh, Bb), 256>>>();

    hn_combine_kernel<<<ROWS / 256, 256>>>();

    finalize_kernel<<<1, 1>>>(beta, out);
}

// round 6
// speedup vs baseline: 8.2120x; 1.0195x over previous
#include <cuda_runtime.h>
#include <cuda_bf16.h>
#include <cuda_fp8.h>
#include <math.h>
#include <stdint.h>

// Problem constants
#define Bb   8
#define SEQ  1024
#define Dd   768
#define Hh   12
#define Zz   64
#define Mm   3072
#define ROWS (Bb * SEQ)           // 8192
#define QKN  (2 * Dd)             // 1536 (Q cols then K cols)
#define NTIL (Mm / 128)           // 24 hopfield n-tiles (128-wide)
#define ATTN_BETA 0.125f          // 1/sqrt(64)
#define LOG2E 1.4426950408889634f
#define LN2   0.6931471805599453f
#define WSCALE 16.0f              // weight pre-scale (power of 2, exact)
#define WUNSCALE 0.0625f

// scratch (device globals: allocation-guard safe)
__device__ uint8_t       g_g8  [(size_t)ROWS * Dd];    // 6.3 MB e4m3
__device__ uint8_t       g_wqk8[QKN * Dd];             // 1.2 MB e4m3 (x16)
__device__ uint8_t       g_whn8[Mm * Dd];              // 2.4 MB e4m3 (x16)
__device__ __nv_bfloat16 g_QKb [(size_t)ROWS * QKN];   // 25 MB
__device__ float         g_hn_part[(size_t)ROWS * NTIL * 2];  // (m,s) pairs
__device__ double g_attn_sum;
__device__ double g_hn_sum;

__global__ void zero_sums_kernel() { g_attn_sum = 0.0; g_hn_sum = 0.0; }

// ---------------------------------------------------------------------------
// fp32 -> e4m3 conversion (with scale), 8 elems/thread
// ---------------------------------------------------------------------------
__global__ void cvt8_kernel(const float* __restrict__ src,
                            uint8_t* __restrict__ dst, int n, float scale) {
    int i = (blockIdx.x * blockDim.x + threadIdx.x) * 8;
    if (i < n) {
        float4 a = *(const float4*)(src + i);
        float4 b = *(const float4*)(src + i + 4);
        __nv_fp8x2_storage_t p0 = __nv_cvt_float2_to_fp8x2(
            make_float2(a.x * scale, a.y * scale), __NV_SATFINITE, __NV_E4M3);
        __nv_fp8x2_storage_t p1 = __nv_cvt_float2_to_fp8x2(
            make_float2(a.z * scale, a.w * scale), __NV_SATFINITE, __NV_E4M3);
        __nv_fp8x2_storage_t p2 = __nv_cvt_float2_to_fp8x2(
            make_float2(b.x * scale, b.y * scale), __NV_SATFINITE, __NV_E4M3);
        __nv_fp8x2_storage_t p3 = __nv_cvt_float2_to_fp8x2(
            make_float2(b.z * scale, b.w * scale), __NV_SATFINITE, __NV_E4M3);
        uint2 o;
        o.x = (uint32_t)p0 | ((uint32_t)p1 << 16);
        o.y = (uint32_t)p2 | ((uint32_t)p3 << 16);
        *(uint2*)(dst + i) = o;
    }
}

// ---------------------------------------------------------------------------
// PTX helpers
// ---------------------------------------------------------------------------
__device__ __forceinline__ uint32_t smem_u32(const void* p) {
    return (uint32_t)__cvta_generic_to_shared(p);
}
__device__ __forceinline__ void ldsm_x4(uint32_t& r0, uint32_t& r1,
                                        uint32_t& r2, uint32_t& r3, uint32_t addr) {
    asm volatile("ldmatrix.sync.aligned.m8n8.x4.shared.b16 {%0,%1,%2,%3}, [%4];"
                 : "=r"(r0), "=r"(r1), "=r"(r2), "=r"(r3) : "r"(addr));
}
__device__ __forceinline__ void mma_bf16(float* d, const uint32_t* a, const uint32_t* b) {
    asm volatile(
        "mma.sync.aligned.m16n8k16.row.col.f32.bf16.bf16.f32 "
        "{%0,%1,%2,%3}, {%4,%5,%6,%7}, {%8,%9}, {%0,%1,%2,%3};"
        : "+f"(d[0]), "+f"(d[1]), "+f"(d[2]), "+f"(d[3])
        : "r"(a[0]), "r"(a[1]), "r"(a[2]), "r"(a[3]), "r"(b[0]), "r"(b[1]));
}
__device__ __forceinline__ void mma_fp8(float* d, const uint32_t* a, const uint32_t* b) {
    asm volatile(
        "mma.sync.aligned.m16n8k32.row.col.f32.e4m3.e4m3.f32 "
        "{%0,%1,%2,%3}, {%4,%5,%6,%7}, {%8,%9}, {%0,%1,%2,%3};"
        : "+f"(d[0]), "+f"(d[1]), "+f"(d[2]), "+f"(d[3])
        : "r"(a[0]), "r"(a[1]), "r"(a[2]), "r"(a[3]), "r"(b[0]), "r"(b[1]));
}
__device__ __forceinline__ void cp16(uint32_t smem, const void* g) {
    asm volatile("cp.async.cg.shared.global [%0], [%1], 16;" :: "r"(smem), "l"(g));
}
__device__ __forceinline__ void cp_commit() {
    asm volatile("cp.async.commit_group;" ::: "memory");
}
template <int N>
__device__ __forceinline__ void cp_wait() {
    asm volatile("cp.async.wait_group %0;" :: "n"(N) : "memory");
}

// ---------------------------------------------------------------------------
// FP8 GEMM: A[M,768](e4m3) * B[N,768](e4m3)^T, 128x128 tile, BK=64 (bytes),
// 256 threads, 8 warps (4x2), warp tile 32x64. cp.async 3-stage ring.
// Weights pre-scaled x16 -> epilogue unscales by 1/16.
// FUSE=false: store bf16 C.  FUSE=true: fused Hopfield row-LSE partials.
// grid = (N/128, M/128)
// ---------------------------------------------------------------------------
#define GSTR  80                 // bytes per smem row (64 + 16 pad)
#define STG_B (128 * GSTR)       // 10240 bytes per operand per stage
#define NCH8  (Dd / 64)          // 12 chunks

template <bool FUSE>
__global__ __launch_bounds__(256, 2)
void gemm_fp8_nt(const uint8_t* __restrict__ A,
                 const uint8_t* __restrict__ B,
                 __nv_bfloat16* __restrict__ C, int N,
                 const float* __restrict__ beta_ptr) {
    extern __shared__ char dynsm[];
    __shared__ float red[2][128][2];   // only used when FUSE

    const int tid  = threadIdx.x;
    const int warp = tid >> 5, lane = tid & 31;
    const int wm = warp >> 1, wn = warp & 1;
    const int m0 = blockIdx.y * 128, n0 = blockIdx.x * 128;

    // cp.async map: 2x16B per thread per operand per chunk
    const int lrow0 = tid >> 2, lc4 = tid & 3;
    const uint8_t* Ag0 = A + (size_t)(m0 + lrow0) * Dd + lc4 * 16;
    const uint8_t* Ag1 = A + (size_t)(m0 + lrow0 + 64) * Dd + lc4 * 16;
    const uint8_t* Bg0 = B + (size_t)(n0 + lrow0) * Dd + lc4 * 16;
    const uint8_t* Bg1 = B + (size_t)(n0 + lrow0 + 64) * Dd + lc4 * 16;
    const uint32_t so0 = (uint32_t)(lrow0 * GSTR + lc4 * 16);
    const uint32_t so1 = so0 + (uint32_t)(64 * GSTR);
    const uint32_t smbase = smem_u32(dynsm);

    float acc[2][8][4];
#pragma unroll
    for (int i = 0; i < 2; ++i)
#pragma unroll
        for (int j = 0; j < 8; ++j)
#pragma unroll
            for (int k = 0; k < 4; ++k) acc[i][j][k] = 0.0f;

    // ldmatrix byte-address components (within a stage)
    const int arow   = wm * 32 + (lane & 15);
    const int acolB  = (lane >> 4) * 16;              // bytes
    const int brow   = wn * 64 + (lane >> 4) * 8 + (lane & 7);
    const int bcolB  = ((lane >> 3) & 1) * 16;        // bytes

    auto issue_chunk = [&](int j, int s) {
        const uint32_t ab = smbase + (uint32_t)(s * 2 * STG_B);
        const uint32_t bb = ab + STG_B;
        const int k0 = j * 64;
        cp16(ab + so0, Ag0 + k0);
        cp16(ab + so1, Ag1 + k0);
        cp16(bb + so0, Bg0 + k0);
        cp16(bb + so1, Bg1 + k0);
    };

    issue_chunk(0, 0); cp_commit();
    issue_chunk(1, 1); cp_commit();

    int stage = 0;
    for (int j = 0; j < NCH8; ++j) {
        cp_wait<1>();
        __syncthreads();
        if (j + 2 < NCH8) issue_chunk(j + 2, (stage + 2) % 3);
        cp_commit();

        const uint32_t ab = smbase + (uint32_t)(stage * 2 * STG_B);
        const uint32_t bb = ab + STG_B;
#pragma unroll
        for (int kk = 0; kk < 64; kk += 32) {          // bytes: two k32 steps
            uint32_t af[2][4];
#pragma unroll
            for (int mt = 0; mt < 2; ++mt)
                ldsm_x4(af[mt][0], af[mt][1], af[mt][2], af[mt][3],
                        ab + (uint32_t)((arow + mt * 16) * GSTR + acolB + kk));
            uint32_t bfr[4][4];
#pragma unroll
            for (int jj = 0; jj < 4; ++jj)
                ldsm_x4(bfr[jj][0], bfr[jj][1], bfr[jj][2], bfr[jj][3],
                        bb + (uint32_t)((brow + jj * 16) * GSTR + bcolB + kk));
#pragma unroll
            for (int mt = 0; mt < 2; ++mt)
#pragma unroll
                for (int jj = 0; jj < 4; ++jj) {
                    mma_fp8(acc[mt][2 * jj],     af[mt], &bfr[jj][0]);
                    mma_fp8(acc[mt][2 * jj + 1], af[mt], &bfr[jj][2]);
                }
        }
        stage = (stage + 1) % 3;
    }

    if (!FUSE) {
#pragma unroll
        for (int mt = 0; mt < 2; ++mt) {
            const int r = m0 + wm * 32 + mt * 16 + (lane >> 2);
#pragma unroll
            for (int nt = 0; nt < 8; ++nt) {
                const int c = n0 + wn * 64 + nt * 8 + (lane & 3) * 2;
                *(__nv_bfloat162*)(C + (size_t)r * N + c) =
                    __float22bfloat162_rn(make_float2(acc[mt][nt][0] * WUNSCALE,
                                                      acc[mt][nt][1] * WUNSCALE));
                *(__nv_bfloat162*)(C + (size_t)(r + 8) * N + c) =
                    __float22bfloat162_rn(make_float2(acc[mt][nt][2] * WUNSCALE,
                                                      acc[mt][nt][3] * WUNSCALE));
            }
        }
    } else {
        // Fused Hopfield LSE partial (exp2 domain); undo weight scale.
        const float SC = beta_ptr[0] * LOG2E * WUNSCALE;
#pragma unroll
        for (int mt = 0; mt < 2; ++mt) {
#pragma unroll
            for (int half = 0; half < 2; ++half) {
                const int rloc = wm * 32 + mt * 16 + half * 8 + (lane >> 2);
                float v[16];
#pragma unroll
                for (int nt = 0; nt < 8; ++nt) {
                    v[2 * nt]     = acc[mt][nt][2 * half]     * SC;
                    v[2 * nt + 1] = acc[mt][nt][2 * half + 1] * SC;
                }
                float lm = v[0];
#pragma unroll
                for (int u = 1; u < 16; ++u) lm = fmaxf(lm, v[u]);
                lm = fmaxf(lm, __shfl_xor_sync(0xffffffffu, lm, 1));
                lm = fmaxf(lm, __shfl_xor_sync(0xffffffffu, lm, 2));
                float ls = 0.0f;
#pragma unroll
                for (int u = 0; u < 16; ++u) ls += exp2f(v[u] - lm);
                ls += __shfl_xor_sync(0xffffffffu, ls, 1);
                ls += __shfl_xor_sync(0xffffffffu, ls, 2);
                if ((lane & 3) == 0) {
                    red[wn][rloc][0] = lm;
                    red[wn][rloc][1] = ls;
                }
            }
        }
        __syncthreads();
        if (tid < 128) {
            float ma = red[0][tid][0], sa = red[0][tid][1];
            float mb = red[1][tid][0], sb = red[1][tid][1];
            float M = fmaxf(ma, mb);
            float S = sa * exp2f(ma - M) + sb * exp2f(mb - M);
            float2* part = (float2*)g_hn_part;
            part[(size_t)(m0 + tid) * NTIL + blockIdx.x] = make_float2(M, S);
        }
    }
}

// ---------------------------------------------------------------------------
// Combine Hopfield partials: one thread per row (8192 rows x 24 tiles).
// ---------------------------------------------------------------------------
__global__ void hn_combine_kernel() {
    const int row = blockIdx.x * 256 + threadIdx.x;
    const float2* part = (const float2*)g_hn_part + (size_t)row * NTIL;
    float M = -1e30f;
#pragma unroll
    for (int t = 0; t < NTIL; ++t) M = fmaxf(M, part[t].x);
    float S = 0.0f;
#pragma unroll
    for (int t = 0; t < NTIL; ++t) S += part[t].y * exp2f(part[t].x - M);
    float lse = (M + log2f(S)) * LN2;

    __shared__ float smr[256];
    smr[threadIdx.x] = lse;
    __syncthreads();
    for (int st = 128; st > 0; st >>= 1) {
        if (threadIdx.x < st) smr[threadIdx.x] += smr[threadIdx.x + st];
        __syncthreads();
    }
    if (threadIdx.x == 0) atomicAdd(&g_hn_sum, (double)smr[0]);
}

// ---------------------------------------------------------------------------
// Fused attention scores (bf16 mma) + online logsumexp (exp2 domain).
// q-tile 128, grid = (8 q-tiles, 12 heads, 8 batch), 256 threads, 8 warps,
// each warp owns 16 q-rows. K streamed in 64-row tiles, cp.async dbl buffer.
// LSE is lane-local in the loop (no shuffles); quad merge at the end.
// ---------------------------------------------------------------------------
#define ALDS 72   // smem row stride (64 + 8 pad)

__global__ __launch_bounds__(256, 2)
void attn_lse_kernel() {
    const int b  = blockIdx.z;
    const int h  = blockIdx.y;
    const int q0 = blockIdx.x * 128;

    __shared__ __nv_bfloat16 Qs[128 * ALDS];
    __shared__ __nv_bfloat16 Ks[2][64 * ALDS];
    __shared__ float red[128];

    const int tid  = threadIdx.x;
    const int wm   = tid >> 5, lane = tid & 31;
    const float SC = ATTN_BETA * LOG2E;

    const __nv_bfloat16* Kbase = g_QKb + (size_t)(b * SEQ) * QKN + Dd + h * Zz;

    auto issue_k = [&](int kt, int s) {
#pragma unroll
        for (int t = 0; t < 2; ++t) {
            int idx = tid + t * 256;
            int row = idx >> 3, ch = (idx & 7) * 8;
            cp16(smem_u32(&Ks[s][row * ALDS + ch]),
                 Kbase + (size_t)(kt * 64 + row) * QKN + ch);
        }
    };

    // Q tile 128x64 via cp.async
    {
#pragma unroll
        for (int i = 0; i < 4; ++i) {
            int idx = tid + i * 256;
            int row = idx >> 3, ch = (idx & 7) * 8;
            cp16(smem_u32(&Qs[row * ALDS + ch]),
                 g_QKb + (size_t)(b * SEQ + q0 + row) * QKN + h * Zz + ch);
        }
        cp_commit();
    }
    issue_k(0, 0); cp_commit();

    cp_wait<1>();        // Q landed
    __syncthreads();

    const uint32_t qs_b = smem_u32(Qs);
    uint32_t qf[4][4];
    {
        const int arow = wm * 16 + (lane & 15);
        const int acol = (lane >> 4) * 8;
#pragma unroll
        for (int zs = 0; zs < 4; ++zs)
            ldsm_x4(qf[zs][0], qf[zs][1], qf[zs][2], qf[zs][3],
                    qs_b + (uint32_t)((arow * ALDS + acol + zs * 16) * 2));
    }

    const int brow = (lane >> 4) * 8 + (lane & 7);
    const int bcol = ((lane >> 3) & 1) * 8;

    float mrun[2] = {-1e30f, -1e30f};
    float srun[2] = {0.0f, 0.0f};

    for (int kt = 0; kt < 16; ++kt) {
        cp_wait<0>();
        __syncthreads();
        if (kt + 1 < 16) issue_k(kt + 1, (kt + 1) & 1);
        cp_commit();

        const uint32_t ks_b = smem_u32(Ks[kt & 1]);

        float acc[8][4];
#pragma unroll
        for (int j = 0; j < 8; ++j)
#pragma unroll
            for (int k = 0; k < 4; ++k) acc[j][k] = 0.0f;

#pragma unroll
        for (int zs = 0; zs < 4; ++zs) {
            uint32_t bfr[4][4];
#pragma unroll
            for (int j = 0; j < 4; ++j)
                ldsm_x4(bfr[j][0], bfr[j][1], bfr[j][2], bfr[j][3],
                        ks_b + (uint32_t)(((brow + j * 16) * ALDS + bcol + zs * 16) * 2));
#pragma unroll
            for (int j = 0; j < 4; ++j) {
                mma_bf16(acc[2 * j],     qf[zs], &bfr[j][0]);
                mma_bf16(acc[2 * j + 1], qf[zs], &bfr[j][2]);
            }
        }

        // lane-local online LSE (no shuffles)
#pragma unroll
        for (int half = 0; half < 2; ++half) {
            float v[16];
#pragma unroll
            for (int j = 0; j < 8; ++j) {
                v[2 * j]     = acc[j][2 * half]     * SC;
                v[2 * j + 1] = acc[j][2 * half + 1] * SC;
            }
            float lm = v[0];
#pragma unroll
            for (int u = 1; u < 16; ++u) lm = fmaxf(lm, v[u]);
            float nm = fmaxf(mrun[half], lm);
            float ls = 0.0f;
#pragma unroll
            for (int u = 0; u < 16; ++u) ls += exp2f(v[u] - nm);
            srun[half] = srun[half] * exp2f(mrun[half] - nm) + ls;
            mrun[half] = nm;
        }
    }

    // merge the 4 lanes of each quad (rows: wm*16 + lane/4 and +8)
#pragma unroll
    for (int half = 0; half < 2; ++half) {
        float m = mrun[half], s = srun[half];
#pragma unroll
        for (int o = 1; o <= 2; o <<= 1) {
            float om = __shfl_xor_sync(0xffffffffu, m, o);
            float os = __shfl_xor_sync(0xffffffffu, s, o);
            float nm = fmaxf(m, om);
            s = s * exp2f(m - nm) + os * exp2f(om - nm);
            m = nm;
        }
        if ((lane & 3) == 0)
            red[wm * 16 + (lane >> 2) + half * 8] = m + log2f(s);
    }
    __syncthreads();

    if (tid < 128) {
        float lse = red[tid] * LN2;
#pragma unroll
        for (int o = 16; o > 0; o >>= 1)
            lse += __shfl_xor_sync(0xffffffffu, lse, o);
        if ((tid & 31) == 0) atomicAdd(&g_attn_sum, (double)lse);
    }
}

__global__ void finalize_kernel(const float* __restrict__ beta_ptr, float* out) {
    double beta = (double)beta_ptr[0];
    out[0] = (float)(-8.0 * g_attn_sum - (1.0 / beta) * g_hn_sum);
}

// ---------------------------------------------------------------------------
extern "C" void kernel_launch(void* const* d_in, const int* in_sizes, int n_in,
                              void* d_out, int out_size) {
    (void)in_sizes; (void)n_in; (void)out_size;
    const float* g    = (const float*)d_in[0];
    const float* wq   = (const float*)d_in[1];
    const float* wk   = (const float*)d_in[2];
    const float* w_hn = (const float*)d_in[3];
    const float* beta = (const float*)d_in[4];
    float* out = (float*)d_out;

    uint8_t *g8, *wqk8, *whn8;
    __nv_bfloat16* QKb;
    cudaGetSymbolAddress((void**)&g8,   g_g8);
    cudaGetSymbolAddress((void**)&wqk8, g_wqk8);
    cudaGetSymbolAddress((void**)&whn8, g_whn8);
    cudaGetSymbolAddress((void**)&QKb,  g_QKb);

    const int SMEM_DYN = 3 * 2 * STG_B;   // 61440 B
    cudaFuncSetAttribute(gemm_fp8_nt<false>,
                         cudaFuncAttributeMaxDynamicSharedMemorySize, SMEM_DYN);
    cudaFuncSetAttribute(gemm_fp8_nt<true>,
                         cudaFuncAttributeMaxDynamicSharedMemorySize, SMEM_DYN);

    zero_sums_kernel<<<1, 1>>>();

    const int ng = ROWS * Dd, nw = Hh * Zz * Dd, nh = Mm * Dd;
    cvt8_kernel<<<(ng / 8 + 255) / 256, 256>>>(g, g8, ng, 1.0f);
    cvt8_kernel<<<(nw / 8 + 255) / 256, 256>>>(wq, wqk8, nw, WSCALE);
    cvt8_kernel<<<(nw / 8 + 255) / 256, 256>>>(wk, wqk8 + nw, nw, WSCALE);
    cvt8_kernel<<<(nh / 8 + 255) / 256, 256>>>(w_hn, whn8, nh, WSCALE);

    // [Q|K] = g @ [wq|wk]^T  (N = 1536), fp8 tensor cores
    gemm_fp8_nt<false><<<dim3(QKN / 128, ROWS / 128), 256, SMEM_DYN>>>(g8, wqk8, QKb, QKN, beta);

    // Hopfield GEMM with fused row-LSE partials, fp8 tensor cores
    gemm_fp8_nt<true><<<dim3(Mm / 128, ROWS / 128), 256, SMEM_DYN>>>(g8, whn8, nullptr, Mm, beta);

    // Attention fused scores + LSE (bf16 HMMA path)
    attn_lse_kernel<<<dim3(SEQ / 128, Hh, Bb), 256>>>();

    hn_combine_kernel<<<ROWS / 256, 256>>>();

    finalize_kernel<<<1, 1>>>(beta, out);
}